// round 5
// baseline (speedup 1.0000x reference)
#include <cuda_runtime.h>
#include <cuda_bf16.h>
#include <math.h>

#define NN 100000
#define NE 1600000
#define NG 512
#define NB 128     // persistent CSR-build blocks (all-resident on 148+ SMs)

// ---------------- device scratch ----------------
__device__ __align__(256) __nv_bfloat162 g_yb[NN * 32];  // y in bf16x2: 128B/node
__device__ __align__(256) float g_t[NN * 64];
__device__ float g_stats[4 * 128];
__device__ float g_scale[64];
__device__ float g_shift[64];
__device__ float g_pooled[NG * 256];
__device__ float g_head1[NG * 64];
__device__ int   g_deg[NN];
__device__ int   g_off[NN + 1];
__device__ int   g_cursor[NN];
__device__ int   g_srcs[NE];
__device__ int   g_bsum[NB];

// grid-barrier state (monotone generation; cnt self-resets)
__device__ volatile unsigned g_gen;
__device__ unsigned g_cnt;

__device__ __forceinline__ void grid_bar(unsigned nb) {
    __syncthreads();
    __threadfence();
    if (threadIdx.x == 0) {
        unsigned gen0 = g_gen;
        if (atomicAdd(&g_cnt, 1u) == nb - 1u) {
            g_cnt = 0u;
            __threadfence();
            g_gen = gen0 + 1u;
        } else {
            while (g_gen == gen0) { __nanosleep(32); }
        }
    }
    __syncthreads();
}

// ---------------- f32x2 helpers ----------------
__device__ __forceinline__ unsigned long long f32x2_dup(float x) {
    unsigned long long r;
    asm("mov.b64 %0, {%1, %1};" : "=l"(r) : "f"(x));
    return r;
}
__device__ __forceinline__ void f32x2_fma(unsigned long long &d,
                                          unsigned long long a, unsigned long long b) {
    asm("fma.rn.f32x2 %0, %1, %2, %0;" : "+l"(d) : "l"(a), "l"(b));
}
__device__ __forceinline__ float2 f32x2_unpack(unsigned long long v) {
    float2 r;
    asm("mov.b64 {%0, %1}, %2;" : "=f"(r.x), "=f"(r.y) : "l"(v));
    return r;
}

// ---------------- persistent CSR build: zero + hist + scan + scatter ----------------
__global__ void __launch_bounds__(1024) csr_build_kernel(const int* __restrict__ ei)
{
    int tid = threadIdx.x;
    int gtid = blockIdx.x * 1024 + tid;
    const int P = NB * 1024;                 // 131072 >= NN

    // phase 0: zero pooled/stats/deg
    for (int i = gtid; i < NG * 256; i += P) g_pooled[i] = 0.f;
    if (gtid < 512) g_stats[gtid] = 0.f;
    if (gtid < NN) g_deg[gtid] = 0;
    grid_bar(gridDim.x);

    // phase 1: degree histogram
    for (int e = gtid; e < NE; e += P)
        atomicAdd(&g_deg[__ldg(&ei[NE + e])], 1);
    grid_bar(gridDim.x);

    // phase 2a: block-level inclusive scan (1 element per thread)
    __shared__ int wsum[32];
    __shared__ int bs[NB];
    int v = (gtid < NN) ? g_deg[gtid] : 0;
    int x = v;
    #pragma unroll
    for (int o = 1; o < 32; o <<= 1) {
        int t = __shfl_up_sync(0xffffffffu, x, o);
        if ((tid & 31) >= o) x += t;
    }
    if ((tid & 31) == 31) wsum[tid >> 5] = x;
    __syncthreads();
    if (tid < 32) {
        int y = wsum[tid];
        #pragma unroll
        for (int o = 1; o < 32; o <<= 1) {
            int t = __shfl_up_sync(0xffffffffu, y, o);
            if (tid >= o) y += t;
        }
        wsum[tid] = y;
    }
    __syncthreads();
    int incl = x + ((tid >= 32) ? wsum[(tid >> 5) - 1] : 0);
    if (tid == 1023) g_bsum[blockIdx.x] = incl;
    grid_bar(gridDim.x);

    // phase 2b: every block redundantly scans the NB block sums
    if (tid < NB) bs[tid] = g_bsum[tid];
    __syncthreads();
    for (int o = 1; o < NB; o <<= 1) {
        int t = 0;
        if (tid < NB && tid >= o) t = bs[tid - o];
        __syncthreads();
        if (tid < NB) bs[tid] += t;
        __syncthreads();
    }
    int base = (blockIdx.x > 0) ? bs[blockIdx.x - 1] : 0;
    if (gtid < NN) {
        int off = base + incl - v;
        g_off[gtid] = off;
        g_cursor[gtid] = off;
    }
    if (gtid == 0) g_off[NN] = NE;
    grid_bar(gridDim.x);

    // phase 3: scatter edge sources into CSR slots
    for (int e = gtid; e < NE; e += P) {
        int s = __ldg(&ei[e]);
        int d = __ldg(&ei[NE + e]);
        int p = atomicAdd(&g_cursor[d], 1);
        g_srcs[p] = s;
    }
}

// ---------------- gemm_pre: y = X @ W1_0 (F=128 -> 64, no bias), bf16 store ----------------
__global__ void __launch_bounds__(256) gemm_pre_kernel(
    const float* __restrict__ X, const float* __restrict__ W, int N)
{
    constexpr int F = 128;
    __shared__ float xs[F * 34];
    __shared__ float ws[F * 64];
    int tid = threadIdx.x;

    const float4* Wv = (const float4*)W;
    float4* wsv = (float4*)ws;
    #pragma unroll
    for (int i = tid; i < F * 16; i += 256) wsv[i] = Wv[i];

    int base = blockIdx.x * 32;
    int n = tid & 31, kq = tid >> 5;
    int row = base + n;
    const float4* Xv = (const float4*)X;
    #pragma unroll
    for (int q = kq; q < F / 4; q += 8) {
        float4 v = make_float4(0.f, 0.f, 0.f, 0.f);
        if (row < N) v = Xv[row * (F / 4) + q];
        xs[(4 * q + 0) * 34 + n] = v.x;
        xs[(4 * q + 1) * 34 + n] = v.y;
        xs[(4 * q + 2) * 34 + n] = v.z;
        xs[(4 * q + 3) * 34 + n] = v.w;
    }
    __syncthreads();

    int w4 = (tid >> 5) * 4;
    int cp = tid & 31;
    int c = cp * 2;
    unsigned long long a00 = 0ull, a01 = 0ull, a10 = 0ull, a11 = 0ull;
    #pragma unroll 4
    for (int k = 0; k < F; k++) {
        unsigned long long xp01 = *(const unsigned long long*)&xs[k * 34 + w4];
        unsigned long long xp23 = *(const unsigned long long*)&xs[k * 34 + w4 + 2];
        float2 wv = *(const float2*)&ws[k * 64 + c];
        unsigned long long wx = f32x2_dup(wv.x), wy = f32x2_dup(wv.y);
        f32x2_fma(a00, xp01, wx); f32x2_fma(a01, xp01, wy);
        f32x2_fma(a10, xp23, wx); f32x2_fma(a11, xp23, wy);
    }
    float2 v00 = f32x2_unpack(a00), v01 = f32x2_unpack(a01);
    float2 v10 = f32x2_unpack(a10), v11 = f32x2_unpack(a11);
    float vals[4][2] = {{v00.x, v01.x}, {v00.y, v01.y}, {v10.x, v11.x}, {v10.y, v11.y}};
    #pragma unroll
    for (int j = 0; j < 4; j++) {
        int r = base + w4 + j;
        if (r < N)
            g_yb[r * 32 + cp] = __floats2bfloat162_rn(vals[j][0], vals[j][1]);
    }
}

// ---------------- aggregate: t[n] = (1+eps)*y[n] + sum_nb y + b1; fused BN stats ----------------
__global__ void __launch_bounds__(256) aggregate_kernel(
    const float* __restrict__ eps_arr, int layer, const float* __restrict__ b1)
{
    __shared__ float ss[128];
    int tid = threadIdx.x;
    if (tid < 128) ss[tid] = 0.f;
    __syncthreads();

    int warp = (blockIdx.x * 256 + tid) >> 5;
    int lane = tid & 31;
    if (warp < NN) {
        float oe = 1.0f + __ldg(&eps_arr[layer]);
        int beg = g_off[warp], end = g_off[warp + 1];
        float2 self = __bfloat1622float2(g_yb[warp * 32 + lane]);
        float2 acc = make_float2(self.x * oe, self.y * oe);
        for (int bse = beg; bse < end; bse += 32) {
            int m = end - bse; if (m > 32) m = 32;
            int idx = (lane < m) ? g_srcs[bse + lane] : 0;
            int t = 0;
            for (; t + 4 <= m; t += 4) {
                int s0 = __shfl_sync(0xffffffffu, idx, t);
                int s1 = __shfl_sync(0xffffffffu, idx, t + 1);
                int s2 = __shfl_sync(0xffffffffu, idx, t + 2);
                int s3 = __shfl_sync(0xffffffffu, idx, t + 3);
                float2 a = __bfloat1622float2(g_yb[s0 * 32 + lane]);
                float2 b = __bfloat1622float2(g_yb[s1 * 32 + lane]);
                float2 cc = __bfloat1622float2(g_yb[s2 * 32 + lane]);
                float2 d = __bfloat1622float2(g_yb[s3 * 32 + lane]);
                acc.x += (a.x + b.x) + (cc.x + d.x);
                acc.y += (a.y + b.y) + (cc.y + d.y);
            }
            for (; t < m; t++) {
                int s0 = __shfl_sync(0xffffffffu, idx, t);
                float2 a = __bfloat1622float2(g_yb[s0 * 32 + lane]);
                acc.x += a.x; acc.y += a.y;
            }
        }
        float2 bb = *(const float2*)&b1[2 * lane];
        acc.x += bb.x; acc.y += bb.y;
        *(float2*)&g_t[warp * 64 + 2 * lane] = acc;
        atomicAdd(&ss[2 * lane], acc.x);
        atomicAdd(&ss[2 * lane + 1], acc.y);
        atomicAdd(&ss[64 + 2 * lane], acc.x * acc.x);
        atomicAdd(&ss[64 + 2 * lane + 1], acc.y * acc.y);
    }
    __syncthreads();
    if (tid < 128) atomicAdd(&g_stats[layer * 128 + tid], ss[tid]);
}

// ---------------- gemm_dual: z=relu(bn(t)); H=relu(z@W2+b2); pool H; y_next=H@W1n (bf16) ----------------
__global__ void __launch_bounds__(256) gemm_dual_kernel(
    const float* __restrict__ W2, const float* __restrict__ B2,
    const int* __restrict__ batch, int pool_off,
    const float* __restrict__ W1n, int has_next, int N,
    int layer, const float* __restrict__ gg, const float* __restrict__ be, float ninv)
{
    __shared__ float xs[64 * 66];
    __shared__ float ws2s[64 * 64];
    __shared__ float ws1s[64 * 64];
    __shared__ float scs[64], shs[64];
    int tid = threadIdx.x;

    {
        const float4* Wv = (const float4*)W2;
        float4* dv = (float4*)ws2s;
        #pragma unroll
        for (int i = tid; i < 1024; i += 256) dv[i] = Wv[i];
    }
    if (has_next) {
        const float4* Wv = (const float4*)W1n;
        float4* dv = (float4*)ws1s;
        #pragma unroll
        for (int i = tid; i < 1024; i += 256) dv[i] = Wv[i];
    }
    if (tid < 64) {
        float mean = g_stats[layer * 128 + tid] * ninv;
        float var  = g_stats[layer * 128 + 64 + tid] * ninv - mean * mean;
        float s = gg[tid] * rsqrtf(var + 1e-5f);
        scs[tid] = s;
        shs[tid] = fmaf(-mean, s, be[tid]);
    }
    __syncthreads();

    int base = blockIdx.x * 64;
    int n = tid & 63, q0 = tid >> 6;
    int row = base + n;
    const float4* Tv = (const float4*)g_t;
    #pragma unroll
    for (int q = q0; q < 16; q += 4) {
        float4 v = make_float4(0.f, 0.f, 0.f, 0.f);
        if (row < N) {
            float4 t = Tv[row * 16 + q];
            int cb = q * 4;
            v.x = fmaxf(fmaf(t.x, scs[cb + 0], shs[cb + 0]), 0.f);
            v.y = fmaxf(fmaf(t.y, scs[cb + 1], shs[cb + 1]), 0.f);
            v.z = fmaxf(fmaf(t.z, scs[cb + 2], shs[cb + 2]), 0.f);
            v.w = fmaxf(fmaf(t.w, scs[cb + 3], shs[cb + 3]), 0.f);
        }
        xs[(4 * q + 0) * 66 + n] = v.x;
        xs[(4 * q + 1) * 66 + n] = v.y;
        xs[(4 * q + 2) * 66 + n] = v.z;
        xs[(4 * q + 3) * 66 + n] = v.w;
    }
    __syncthreads();

    int w8 = (tid >> 5) * 8;
    int cp = tid & 31;
    int c = cp * 2;
    float2 bb = *(const float2*)&B2[c];
    unsigned long long acc[4][2];
    #pragma unroll
    for (int p = 0; p < 4; p++) { acc[p][0] = f32x2_dup(bb.x); acc[p][1] = f32x2_dup(bb.y); }
    #pragma unroll 4
    for (int k = 0; k < 64; k++) {
        float2 wv = *(const float2*)&ws2s[k * 64 + c];
        unsigned long long wx = f32x2_dup(wv.x), wy = f32x2_dup(wv.y);
        #pragma unroll
        for (int p = 0; p < 4; p++) {
            unsigned long long xp = *(const unsigned long long*)&xs[k * 66 + w8 + 2 * p];
            f32x2_fma(acc[p][0], xp, wx);
            f32x2_fma(acc[p][1], xp, wy);
        }
    }
    float H[8][2];
    #pragma unroll
    for (int p = 0; p < 4; p++) {
        float2 u0 = f32x2_unpack(acc[p][0]);
        float2 u1 = f32x2_unpack(acc[p][1]);
        H[2 * p + 0][0] = fmaxf(u0.x, 0.f); H[2 * p + 0][1] = fmaxf(u1.x, 0.f);
        H[2 * p + 1][0] = fmaxf(u0.y, 0.f); H[2 * p + 1][1] = fmaxf(u1.y, 0.f);
    }

    // pooling (batch sorted -> run-compressed atomics)
    int rbase = base + w8;
    int bprev = -1; float p0 = 0.f, p1 = 0.f;
    #pragma unroll
    for (int j = 0; j < 8; j++) {
        int r = rbase + j;
        if (r < N) {
            int bg = batch[r];
            if (bg != bprev) {
                if (bprev >= 0)
                    atomicAdd((float2*)&g_pooled[bprev * 256 + pool_off + c], make_float2(p0, p1));
                bprev = bg; p0 = 0.f; p1 = 0.f;
            }
            p0 += H[j][0]; p1 += H[j][1];
        }
    }
    if (bprev >= 0)
        atomicAdd((float2*)&g_pooled[bprev * 256 + pool_off + c], make_float2(p0, p1));

    if (has_next) {
        #pragma unroll
        for (int p = 0; p < 4; p++) {
            *(float2*)&xs[c * 66 + w8 + 2 * p]       = make_float2(H[2 * p][0], H[2 * p + 1][0]);
            *(float2*)&xs[(c + 1) * 66 + w8 + 2 * p] = make_float2(H[2 * p][1], H[2 * p + 1][1]);
        }
        __syncwarp();
        unsigned long long acc2[4][2];
        #pragma unroll
        for (int p = 0; p < 4; p++) { acc2[p][0] = 0ull; acc2[p][1] = 0ull; }
        #pragma unroll 4
        for (int k = 0; k < 64; k++) {
            float2 wv = *(const float2*)&ws1s[k * 64 + c];
            unsigned long long wx = f32x2_dup(wv.x), wy = f32x2_dup(wv.y);
            #pragma unroll
            for (int p = 0; p < 4; p++) {
                unsigned long long xp = *(const unsigned long long*)&xs[k * 66 + w8 + 2 * p];
                f32x2_fma(acc2[p][0], xp, wx);
                f32x2_fma(acc2[p][1], xp, wy);
            }
        }
        #pragma unroll
        for (int p = 0; p < 4; p++) {
            float2 u0 = f32x2_unpack(acc2[p][0]);
            float2 u1 = f32x2_unpack(acc2[p][1]);
            int r0 = rbase + 2 * p, r1 = r0 + 1;
            if (r0 < N) g_yb[r0 * 32 + cp] = __floats2bfloat162_rn(u0.x, u1.x);
            if (r1 < N) g_yb[r1 * 32 + cp] = __floats2bfloat162_rn(u0.y, u1.y);
        }
    }
}

// ---------------- fused head: head1 GEMM -> BN -> final GEMM + log_softmax ----------------
// 64 blocks x 256 threads, persistent with 2 grid barriers
__global__ void __launch_bounds__(256) head_kernel(
    const float* __restrict__ W1, const float* __restrict__ B1,
    const float* __restrict__ gg, const float* __restrict__ be,
    const float* __restrict__ W2, const float* __restrict__ B2,
    float* __restrict__ out)
{
    int tid = threadIdx.x, b = blockIdx.x;

    // phase A: head1 = pooled @ W1 + B1 ; 8 graphs per block
    {
        __shared__ float xsA[8 * 256];
        for (int i = tid; i < 2048; i += 256) xsA[i] = g_pooled[b * 2048 + i];
        __syncthreads();
        int g = tid >> 5;
        int c = (tid & 31) * 2;
        float2 a = *(const float2*)&B1[c];
        #pragma unroll 4
        for (int k = 0; k < 256; k++) {
            float xv = xsA[g * 256 + k];
            float2 wv = *(const float2*)&W1[k * 64 + c];
            a.x = fmaf(xv, wv.x, a.x);
            a.y = fmaf(xv, wv.y, a.y);
        }
        *(float2*)&g_head1[(b * 8 + g) * 64 + c] = a;
    }
    grid_bar(gridDim.x);

    // phase B: exact two-pass BN for channel b
    {
        __shared__ float red[256];
        float v0 = g_head1[tid * 64 + b];
        float v1 = g_head1[(tid + 256) * 64 + b];
        red[tid] = v0 + v1;
        __syncthreads();
        for (int o = 128; o > 0; o >>= 1) { if (tid < o) red[tid] += red[tid + o]; __syncthreads(); }
        float mean = red[0] * (1.0f / 512.0f);
        __syncthreads();
        float d0 = v0 - mean, d1 = v1 - mean;
        red[tid] = d0 * d0 + d1 * d1;
        __syncthreads();
        for (int o = 128; o > 0; o >>= 1) { if (tid < o) red[tid] += red[tid + o]; __syncthreads(); }
        if (tid == 0) {
            float var = red[0] * (1.0f / 512.0f);
            float s = gg[b] * rsqrtf(var + 1e-5f);
            g_scale[b] = s;
            g_shift[b] = fmaf(-mean, s, be[b]);
        }
    }
    grid_bar(gridDim.x);

    // phase C: relu(bn) @ W2 + B2, log_softmax ; 8 graphs per block, 1 warp each
    {
        __shared__ float hn[8][64];
        __shared__ float lg[8][10];
        int g = tid >> 5, lane = tid & 31;
        int gph = b * 8 + g;
        int c = lane * 2;
        float2 h = *(const float2*)&g_head1[gph * 64 + c];
        hn[g][c]     = fmaxf(fmaf(h.x, g_scale[c],     g_shift[c]),     0.f);
        hn[g][c + 1] = fmaxf(fmaf(h.y, g_scale[c + 1], g_shift[c + 1]), 0.f);
        __syncwarp();
        if (lane < 10) {
            float a = B2[lane];
            #pragma unroll
            for (int k = 0; k < 64; k++) a = fmaf(hn[g][k], __ldg(&W2[k * 10 + lane]), a);
            lg[g][lane] = a;
        }
        __syncwarp();
        if (lane == 0) {
            float m = lg[g][0];
            #pragma unroll
            for (int j = 1; j < 10; j++) m = fmaxf(m, lg[g][j]);
            float ssum = 0.f;
            #pragma unroll
            for (int j = 0; j < 10; j++) ssum += expf(lg[g][j] - m);
            float lse = m + logf(ssum);
            #pragma unroll
            for (int j = 0; j < 10; j++) out[gph * 10 + j] = lg[g][j] - lse;
        }
    }
}

// ---------------- launch ----------------
extern "C" void kernel_launch(void* const* d_in, const int* in_sizes, int n_in,
                              void* d_out, int out_size)
{
    const float* x     = (const float*)d_in[0];
    const int*   ei    = (const int*)d_in[1];
    const int*   batch = (const int*)d_in[2];
    const float* eps   = (const float*)d_in[3];

    // 1: CSR build (zero + hist + scan + scatter in one persistent kernel)
    csr_build_kernel<<<NB, 1024>>>(ei);

    // 2: y0 = x @ W1_0 (stored bf16)
    gemm_pre_kernel<<<(NN + 31) / 32, 256>>>(x, (const float*)d_in[4], NN);

    for (int l = 0; l < 4; l++) {
        const float *b1, *gg, *be, *W2, *b2;
        if (l == 0) {
            b1 = (const float*)d_in[5];
            gg = (const float*)d_in[6]; be = (const float*)d_in[7];
            W2 = (const float*)d_in[8]; b2 = (const float*)d_in[9];
        } else {
            int j = l - 1;
            b1 = (const float*)d_in[11] + j * 64;
            gg = (const float*)d_in[12] + j * 64; be = (const float*)d_in[13] + j * 64;
            W2 = (const float*)d_in[14] + j * 64 * 64; b2 = (const float*)d_in[15] + j * 64;
        }
        const float* W1n = (l < 3) ? ((const float*)d_in[10] + l * 64 * 64) : (const float*)d_in[10];
        int has_next = (l < 3) ? 1 : 0;

        // 3,5,7,9: aggregate ; 4,6,8,10: gemm_dual  (slot 4 = gemm_dual layer 0 -> profiled)
        aggregate_kernel<<<(NN * 32 + 255) / 256, 256>>>(eps, l, b1);
        gemm_dual_kernel<<<(NN + 63) / 64, 256>>>(W2, b2, batch, l * 64, W1n, has_next, NN,
                                                  l, gg, be, 1.0f / (float)NN);
    }

    // 11: fused head
    head_kernel<<<64, 256>>>((const float*)d_in[16], (const float*)d_in[17],
                             (const float*)d_in[18], (const float*)d_in[19],
                             (const float*)d_in[20], (const float*)d_in[21],
                             (float*)d_out);
}

// round 6
// speedup vs baseline: 1.3988x; 1.3988x over previous
#include <cuda_runtime.h>
#include <cuda_bf16.h>
#include <math.h>

#define NN 100000
#define NE 1600000
#define NG 512
#define NSB 98   // scan blocks of 1024 -> covers 100352 >= NN

// ---------------- device scratch ----------------
__device__ __align__(256) __nv_bfloat162 g_yb[NN * 32];  // y in bf16x2: 128B/node
__device__ __align__(256) float g_t[NN * 64];
__device__ float g_stats[4 * 128];
__device__ float g_scale[64];
__device__ float g_shift[64];
__device__ float g_pooled[NG * 256];
__device__ float g_head1[NG * 64];
__device__ int   g_deg[NN];
__device__ int   g_off[NN + 1];
__device__ int   g_cursor[NN];
__device__ int   g_srcs[NE];
__device__ int   g_bsum[NSB];
__device__ int   g_boff[NSB];

// ---------------- f32x2 helpers ----------------
__device__ __forceinline__ unsigned long long f32x2_dup(float x) {
    unsigned long long r;
    asm("mov.b64 %0, {%1, %1};" : "=l"(r) : "f"(x));
    return r;
}
__device__ __forceinline__ void f32x2_fma(unsigned long long &d,
                                          unsigned long long a, unsigned long long b) {
    asm("fma.rn.f32x2 %0, %1, %2, %0;" : "+l"(d) : "l"(a), "l"(b));
}
__device__ __forceinline__ float2 f32x2_unpack(unsigned long long v) {
    float2 r;
    asm("mov.b64 {%0, %1}, %2;" : "=f"(r.x), "=f"(r.y) : "l"(v));
    return r;
}

// ---------------- fused zero kernel ----------------
#define ZW (131072 + 512 + NN)
__global__ void zero_all_kernel() {
    int i = blockIdx.x * 256 + threadIdx.x;
    if (i < 131072) g_pooled[i] = 0.f;
    else if (i < 131072 + 512) g_stats[i - 131072] = 0.f;
    else if (i < ZW) g_deg[i - 131072 - 512] = 0;
}

// ---------------- CSR build (round-4 streamed version) ----------------
__global__ void hist_kernel(const int* __restrict__ ei) {
    int e = blockIdx.x * 256 + threadIdx.x;
    if (e < NE) atomicAdd(&g_deg[ei[NE + e]], 1);
}
__global__ void scan1_kernel() {                  // <<<NSB,1024>>>
    __shared__ int wsum[32];
    int tid = threadIdx.x;
    int i = blockIdx.x * 1024 + tid;
    int v = (i < NN) ? g_deg[i] : 0;
    int x = v;
    #pragma unroll
    for (int o = 1; o < 32; o <<= 1) {
        int t = __shfl_up_sync(0xffffffffu, x, o);
        if ((tid & 31) >= o) x += t;
    }
    if ((tid & 31) == 31) wsum[tid >> 5] = x;
    __syncthreads();
    if (tid < 32) {
        int y = wsum[tid];
        #pragma unroll
        for (int o = 1; o < 32; o <<= 1) {
            int t = __shfl_up_sync(0xffffffffu, y, o);
            if (tid >= o) y += t;
        }
        wsum[tid] = y;
    }
    __syncthreads();
    int base = (tid >= 32) ? wsum[(tid >> 5) - 1] : 0;
    int incl = x + base;
    if (i < NN) g_off[i] = incl - v;
    if (tid == 1023) g_bsum[blockIdx.x] = incl;
}
__global__ void scan2_kernel() {                  // <<<1,128>>>
    __shared__ int s[128];
    int tid = threadIdx.x;
    int v = (tid < NSB) ? g_bsum[tid] : 0;
    s[tid] = v; __syncthreads();
    for (int off = 1; off < 128; off <<= 1) {
        int t = (tid >= off) ? s[tid - off] : 0;
        __syncthreads();
        s[tid] += t;
        __syncthreads();
    }
    if (tid < NSB) g_boff[tid] = s[tid] - v;
}
__global__ void scan3_kernel() {                  // <<<NSB,1024>>>
    int i = blockIdx.x * 1024 + threadIdx.x;
    if (i < NN) {
        int v = g_off[i] + g_boff[blockIdx.x];
        g_off[i] = v;
        g_cursor[i] = v;
    }
    if (i == 0) g_off[NN] = NE;
}
__global__ void csr_scatter_kernel(const int* __restrict__ ei) {
    int e = blockIdx.x * 256 + threadIdx.x;
    if (e < NE) {
        int s = ei[e];
        int d = ei[NE + e];
        int p = atomicAdd(&g_cursor[d], 1);
        g_srcs[p] = s;
    }
}

// ---------------- gemm_pre: y = X @ W1_0 (F=128 -> 64, no bias), bf16 store ----------------
__global__ void __launch_bounds__(256) gemm_pre_kernel(
    const float* __restrict__ X, const float* __restrict__ W, int N)
{
    constexpr int F = 128;
    __shared__ float xs[F * 36];       // stride 36 -> 16B-aligned node quads
    __shared__ float ws[F * 64];
    int tid = threadIdx.x;

    const float4* Wv = (const float4*)W;
    float4* wsv = (float4*)ws;
    #pragma unroll
    for (int i = tid; i < F * 16; i += 256) wsv[i] = Wv[i];

    int base = blockIdx.x * 32;
    int n = tid & 31, kq = tid >> 5;
    int row = base + n;
    const float4* Xv = (const float4*)X;
    #pragma unroll
    for (int q = kq; q < F / 4; q += 8) {
        float4 v = make_float4(0.f, 0.f, 0.f, 0.f);
        if (row < N) v = Xv[row * (F / 4) + q];
        xs[(4 * q + 0) * 36 + n] = v.x;
        xs[(4 * q + 1) * 36 + n] = v.y;
        xs[(4 * q + 2) * 36 + n] = v.z;
        xs[(4 * q + 3) * 36 + n] = v.w;
    }
    __syncthreads();

    int w4 = (tid >> 5) * 4;
    int cp = tid & 31;
    int c = cp * 2;
    unsigned long long a00 = 0ull, a01 = 0ull, a10 = 0ull, a11 = 0ull;
    #pragma unroll 4
    for (int k = 0; k < F; k++) {
        ulonglong2 xa = *(const ulonglong2*)&xs[k * 36 + w4];   // LDS.128 broadcast: 4 nodes
        float2 wv = *(const float2*)&ws[k * 64 + c];
        unsigned long long wx = f32x2_dup(wv.x), wy = f32x2_dup(wv.y);
        f32x2_fma(a00, xa.x, wx); f32x2_fma(a01, xa.x, wy);
        f32x2_fma(a10, xa.y, wx); f32x2_fma(a11, xa.y, wy);
    }
    float2 v00 = f32x2_unpack(a00), v01 = f32x2_unpack(a01);
    float2 v10 = f32x2_unpack(a10), v11 = f32x2_unpack(a11);
    float vals[4][2] = {{v00.x, v01.x}, {v00.y, v01.y}, {v10.x, v11.x}, {v10.y, v11.y}};
    #pragma unroll
    for (int j = 0; j < 4; j++) {
        int r = base + w4 + j;
        if (r < N)
            g_yb[r * 32 + cp] = __floats2bfloat162_rn(vals[j][0], vals[j][1]);
    }
}

// ---------------- aggregate: t[n] = (1+eps)*y[n] + sum_nb y + b1; fused BN stats ----------------
__global__ void __launch_bounds__(256) aggregate_kernel(
    const float* __restrict__ eps_arr, int layer, const float* __restrict__ b1)
{
    __shared__ float ss[128];
    int tid = threadIdx.x;
    if (tid < 128) ss[tid] = 0.f;
    __syncthreads();

    int warp = (blockIdx.x * 256 + tid) >> 5;
    int lane = tid & 31;
    if (warp < NN) {
        float oe = 1.0f + __ldg(&eps_arr[layer]);
        int beg = g_off[warp], end = g_off[warp + 1];
        float2 self = __bfloat1622float2(g_yb[warp * 32 + lane]);
        float2 acc = make_float2(self.x * oe, self.y * oe);
        for (int bse = beg; bse < end; bse += 32) {
            int m = end - bse; if (m > 32) m = 32;
            int idx = (lane < m) ? g_srcs[bse + lane] : 0;
            int t = 0;
            for (; t + 4 <= m; t += 4) {
                int s0 = __shfl_sync(0xffffffffu, idx, t);
                int s1 = __shfl_sync(0xffffffffu, idx, t + 1);
                int s2 = __shfl_sync(0xffffffffu, idx, t + 2);
                int s3 = __shfl_sync(0xffffffffu, idx, t + 3);
                float2 a = __bfloat1622float2(g_yb[s0 * 32 + lane]);
                float2 b = __bfloat1622float2(g_yb[s1 * 32 + lane]);
                float2 cc = __bfloat1622float2(g_yb[s2 * 32 + lane]);
                float2 d = __bfloat1622float2(g_yb[s3 * 32 + lane]);
                acc.x += (a.x + b.x) + (cc.x + d.x);
                acc.y += (a.y + b.y) + (cc.y + d.y);
            }
            for (; t < m; t++) {
                int s0 = __shfl_sync(0xffffffffu, idx, t);
                float2 a = __bfloat1622float2(g_yb[s0 * 32 + lane]);
                acc.x += a.x; acc.y += a.y;
            }
        }
        float2 bb = *(const float2*)&b1[2 * lane];
        acc.x += bb.x; acc.y += bb.y;
        *(float2*)&g_t[warp * 64 + 2 * lane] = acc;
        atomicAdd(&ss[2 * lane], acc.x);
        atomicAdd(&ss[2 * lane + 1], acc.y);
        atomicAdd(&ss[64 + 2 * lane], acc.x * acc.x);
        atomicAdd(&ss[64 + 2 * lane + 1], acc.y * acc.y);
    }
    __syncthreads();
    if (tid < 128) atomicAdd(&g_stats[layer * 128 + tid], ss[tid]);
}

// ---------------- gemm_dual: z=relu(bn(t)); H=relu(z@W2+b2); pool H; y_next=H@W1n (bf16) ----------------
__global__ void __launch_bounds__(256) gemm_dual_kernel(
    const float* __restrict__ W2, const float* __restrict__ B2,
    const int* __restrict__ batch, int pool_off,
    const float* __restrict__ W1n, int has_next, int N,
    int layer, const float* __restrict__ gg, const float* __restrict__ be, float ninv)
{
    __shared__ float xs[64 * 68];     // stride 68 -> 16B-aligned node quads
    __shared__ float ws2s[64 * 64];
    __shared__ float ws1s[64 * 64];
    __shared__ float scs[64], shs[64];
    int tid = threadIdx.x;

    {
        const float4* Wv = (const float4*)W2;
        float4* dv = (float4*)ws2s;
        #pragma unroll
        for (int i = tid; i < 1024; i += 256) dv[i] = Wv[i];
    }
    if (has_next) {
        const float4* Wv = (const float4*)W1n;
        float4* dv = (float4*)ws1s;
        #pragma unroll
        for (int i = tid; i < 1024; i += 256) dv[i] = Wv[i];
    }
    if (tid < 64) {
        float mean = g_stats[layer * 128 + tid] * ninv;
        float var  = g_stats[layer * 128 + 64 + tid] * ninv - mean * mean;
        float s = gg[tid] * rsqrtf(var + 1e-5f);
        scs[tid] = s;
        shs[tid] = fmaf(-mean, s, be[tid]);
    }
    __syncthreads();

    int base = blockIdx.x * 64;
    int n = tid & 63, q0 = tid >> 6;
    int row = base + n;
    const float4* Tv = (const float4*)g_t;
    #pragma unroll
    for (int q = q0; q < 16; q += 4) {
        float4 v = make_float4(0.f, 0.f, 0.f, 0.f);
        if (row < N) {
            float4 t = Tv[row * 16 + q];
            int cb = q * 4;
            v.x = fmaxf(fmaf(t.x, scs[cb + 0], shs[cb + 0]), 0.f);
            v.y = fmaxf(fmaf(t.y, scs[cb + 1], shs[cb + 1]), 0.f);
            v.z = fmaxf(fmaf(t.z, scs[cb + 2], shs[cb + 2]), 0.f);
            v.w = fmaxf(fmaf(t.w, scs[cb + 3], shs[cb + 3]), 0.f);
        }
        xs[(4 * q + 0) * 68 + n] = v.x;
        xs[(4 * q + 1) * 68 + n] = v.y;
        xs[(4 * q + 2) * 68 + n] = v.z;
        xs[(4 * q + 3) * 68 + n] = v.w;
    }
    __syncthreads();

    int w8 = (tid >> 5) * 8;
    int cp = tid & 31;
    int c = cp * 2;
    float2 bb = *(const float2*)&B2[c];
    unsigned long long acc[4][2];
    #pragma unroll
    for (int p = 0; p < 4; p++) { acc[p][0] = f32x2_dup(bb.x); acc[p][1] = f32x2_dup(bb.y); }
    #pragma unroll 4
    for (int k = 0; k < 64; k++) {
        ulonglong2 xa = *(const ulonglong2*)&xs[k * 68 + w8];       // nodes 0-3 (LDS.128)
        ulonglong2 xb = *(const ulonglong2*)&xs[k * 68 + w8 + 4];   // nodes 4-7 (LDS.128)
        float2 wv = *(const float2*)&ws2s[k * 64 + c];
        unsigned long long wx = f32x2_dup(wv.x), wy = f32x2_dup(wv.y);
        f32x2_fma(acc[0][0], xa.x, wx); f32x2_fma(acc[0][1], xa.x, wy);
        f32x2_fma(acc[1][0], xa.y, wx); f32x2_fma(acc[1][1], xa.y, wy);
        f32x2_fma(acc[2][0], xb.x, wx); f32x2_fma(acc[2][1], xb.x, wy);
        f32x2_fma(acc[3][0], xb.y, wx); f32x2_fma(acc[3][1], xb.y, wy);
    }
    float H[8][2];
    #pragma unroll
    for (int p = 0; p < 4; p++) {
        float2 u0 = f32x2_unpack(acc[p][0]);
        float2 u1 = f32x2_unpack(acc[p][1]);
        H[2 * p + 0][0] = fmaxf(u0.x, 0.f); H[2 * p + 0][1] = fmaxf(u1.x, 0.f);
        H[2 * p + 1][0] = fmaxf(u0.y, 0.f); H[2 * p + 1][1] = fmaxf(u1.y, 0.f);
    }

    // pooling (batch sorted -> run-compressed atomics)
    int rbase = base + w8;
    int bprev = -1; float p0 = 0.f, p1 = 0.f;
    #pragma unroll
    for (int j = 0; j < 8; j++) {
        int r = rbase + j;
        if (r < N) {
            int bg = batch[r];
            if (bg != bprev) {
                if (bprev >= 0)
                    atomicAdd((float2*)&g_pooled[bprev * 256 + pool_off + c], make_float2(p0, p1));
                bprev = bg; p0 = 0.f; p1 = 0.f;
            }
            p0 += H[j][0]; p1 += H[j][1];
        }
    }
    if (bprev >= 0)
        atomicAdd((float2*)&g_pooled[bprev * 256 + pool_off + c], make_float2(p0, p1));

    if (has_next) {
        #pragma unroll
        for (int p = 0; p < 4; p++) {
            *(float2*)&xs[c * 68 + w8 + 2 * p]       = make_float2(H[2 * p][0], H[2 * p + 1][0]);
            *(float2*)&xs[(c + 1) * 68 + w8 + 2 * p] = make_float2(H[2 * p][1], H[2 * p + 1][1]);
        }
        __syncwarp();
        unsigned long long acc2[4][2];
        #pragma unroll
        for (int p = 0; p < 4; p++) { acc2[p][0] = 0ull; acc2[p][1] = 0ull; }
        #pragma unroll 4
        for (int k = 0; k < 64; k++) {
            ulonglong2 xa = *(const ulonglong2*)&xs[k * 68 + w8];
            ulonglong2 xb = *(const ulonglong2*)&xs[k * 68 + w8 + 4];
            float2 wv = *(const float2*)&ws1s[k * 64 + c];
            unsigned long long wx = f32x2_dup(wv.x), wy = f32x2_dup(wv.y);
            f32x2_fma(acc2[0][0], xa.x, wx); f32x2_fma(acc2[0][1], xa.x, wy);
            f32x2_fma(acc2[1][0], xa.y, wx); f32x2_fma(acc2[1][1], xa.y, wy);
            f32x2_fma(acc2[2][0], xb.x, wx); f32x2_fma(acc2[2][1], xb.x, wy);
            f32x2_fma(acc2[3][0], xb.y, wx); f32x2_fma(acc2[3][1], xb.y, wy);
        }
        #pragma unroll
        for (int p = 0; p < 4; p++) {
            float2 u0 = f32x2_unpack(acc2[p][0]);
            float2 u1 = f32x2_unpack(acc2[p][1]);
            int r0 = rbase + 2 * p, r1 = r0 + 1;
            if (r0 < N) g_yb[r0 * 32 + cp] = __floats2bfloat162_rn(u0.x, u1.x);
            if (r1 < N) g_yb[r1 * 32 + cp] = __floats2bfloat162_rn(u0.y, u1.y);
        }
    }
}

// ---------------- head (round-4 streamed version) ----------------
__global__ void head1_kernel(const float* __restrict__ W, const float* __restrict__ B)
{
    int gph = blockIdx.x, c = threadIdx.x;   // <<<512,64>>>
    __shared__ float xs[256];
    #pragma unroll
    for (int i = c; i < 256; i += 64) xs[i] = g_pooled[gph * 256 + i];
    __syncthreads();
    float a = B[c];
    #pragma unroll 4
    for (int k = 0; k < 256; k++) a = fmaf(xs[k], __ldg(&W[k * 64 + c]), a);
    g_head1[gph * 64 + c] = a;
}

__global__ void head_bn_kernel(const float* __restrict__ g, const float* __restrict__ be)
{
    int c = blockIdx.x; int t = threadIdx.x;  // <<<64,256>>>
    __shared__ float red[256];
    float v0 = g_head1[t * 64 + c];
    float v1 = g_head1[(t + 256) * 64 + c];
    red[t] = v0 + v1;
    __syncthreads();
    for (int o = 128; o > 0; o >>= 1) { if (t < o) red[t] += red[t + o]; __syncthreads(); }
    float mean = red[0] * (1.0f / 512.0f);
    __syncthreads();
    float d0 = v0 - mean, d1 = v1 - mean;
    red[t] = d0 * d0 + d1 * d1;
    __syncthreads();
    for (int o = 128; o > 0; o >>= 1) { if (t < o) red[t] += red[t + o]; __syncthreads(); }
    if (t == 0) {
        float var = red[0] * (1.0f / 512.0f);
        float s = g[c] * rsqrtf(var + 1e-5f);
        g_scale[c] = s;
        g_shift[c] = fmaf(-mean, s, be[c]);
    }
}

__global__ void head_final_kernel(const float* __restrict__ W, const float* __restrict__ B,
                                  float* __restrict__ out)
{
    int gph = blockIdx.x; int c = threadIdx.x;   // <<<512,64>>>
    __shared__ float hn[64];
    __shared__ float logits[10];
    hn[c] = fmaxf(fmaf(g_head1[gph * 64 + c], g_scale[c], g_shift[c]), 0.f);
    __syncthreads();
    if (c < 10) {
        float a = B[c];
        #pragma unroll
        for (int k = 0; k < 64; k++) a = fmaf(hn[k], W[k * 10 + c], a);
        logits[c] = a;
    }
    __syncthreads();
    if (c == 0) {
        float m = logits[0];
        #pragma unroll
        for (int j = 1; j < 10; j++) m = fmaxf(m, logits[j]);
        float ssum = 0.f;
        #pragma unroll
        for (int j = 0; j < 10; j++) ssum += expf(logits[j] - m);
        float lse = m + logf(ssum);
        #pragma unroll
        for (int j = 0; j < 10; j++) out[gph * 10 + j] = logits[j] - lse;
    }
}

// ---------------- launch ----------------
extern "C" void kernel_launch(void* const* d_in, const int* in_sizes, int n_in,
                              void* d_out, int out_size)
{
    const float* x     = (const float*)d_in[0];
    const int*   ei    = (const int*)d_in[1];
    const int*   batch = (const int*)d_in[2];
    const float* eps   = (const float*)d_in[3];

    zero_all_kernel<<<(ZW + 255) / 256, 256>>>();                 // 1
    hist_kernel<<<(NE + 255) / 256, 256>>>(ei);                   // 2
    scan1_kernel<<<NSB, 1024>>>();                                // 3
    // gemm_pre is independent of the scans -> slot 4 (ncu profiles this one)
    gemm_pre_kernel<<<(NN + 31) / 32, 256>>>(x, (const float*)d_in[4], NN);  // 4
    scan2_kernel<<<1, 128>>>();                                   // 5
    scan3_kernel<<<NSB, 1024>>>();                                // 6
    csr_scatter_kernel<<<(NE + 255) / 256, 256>>>(ei);            // 7

    for (int l = 0; l < 4; l++) {
        const float *b1, *gg, *be, *W2, *b2;
        if (l == 0) {
            b1 = (const float*)d_in[5];
            gg = (const float*)d_in[6]; be = (const float*)d_in[7];
            W2 = (const float*)d_in[8]; b2 = (const float*)d_in[9];
        } else {
            int j = l - 1;
            b1 = (const float*)d_in[11] + j * 64;
            gg = (const float*)d_in[12] + j * 64; be = (const float*)d_in[13] + j * 64;
            W2 = (const float*)d_in[14] + j * 64 * 64; b2 = (const float*)d_in[15] + j * 64;
        }
        const float* W1n = (l < 3) ? ((const float*)d_in[10] + l * 64 * 64) : (const float*)d_in[10];
        int has_next = (l < 3) ? 1 : 0;

        aggregate_kernel<<<(NN * 32 + 255) / 256, 256>>>(eps, l, b1);
        gemm_dual_kernel<<<(NN + 63) / 64, 256>>>(W2, b2, batch, l * 64, W1n, has_next, NN,
                                                  l, gg, be, 1.0f / (float)NN);
    }

    head1_kernel<<<NG, 64>>>((const float*)d_in[16], (const float*)d_in[17]);
    head_bn_kernel<<<64, 256>>>((const float*)d_in[18], (const float*)d_in[19]);
    head_final_kernel<<<NG, 64>>>((const float*)d_in[20], (const float*)d_in[21], (float*)d_out);
}

// round 7
// speedup vs baseline: 1.4160x; 1.0123x over previous
#include <cuda_runtime.h>
#include <cuda_bf16.h>
#include <math.h>

#define NN 100000
#define NE 1600000
#define NG 512
#define NSB 98   // scan blocks of 1024 -> covers 100352 >= NN

// ---------------- device scratch ----------------
__device__ __align__(256) __nv_bfloat162 g_yb[NN * 32];  // y in bf16x2: 128B/node
__device__ __align__(256) float g_t[NN * 64];
__device__ float g_stats[4 * 128];
__device__ float g_scale[64];
__device__ float g_shift[64];
__device__ float g_pooled[NG * 256];
__device__ float g_head1[NG * 64];
__device__ int   g_deg[NN];
__device__ int   g_off[NN + 1];
__device__ int   g_cursor[NN];
__device__ int   g_srcs[NE];
__device__ int   g_bsum[NSB];
__device__ int   g_boff[NSB];

// ---------------- f32x2 helpers ----------------
__device__ __forceinline__ unsigned long long f32x2_dup(float x) {
    unsigned long long r;
    asm("mov.b64 %0, {%1, %1};" : "=l"(r) : "f"(x));
    return r;
}
__device__ __forceinline__ void f32x2_fma(unsigned long long &d,
                                          unsigned long long a, unsigned long long b) {
    asm("fma.rn.f32x2 %0, %1, %2, %0;" : "+l"(d) : "l"(a), "l"(b));
}
__device__ __forceinline__ float2 f32x2_unpack(unsigned long long v) {
    float2 r;
    asm("mov.b64 {%0, %1}, %2;" : "=f"(r.x), "=f"(r.y) : "l"(v));
    return r;
}

// ---------------- fused zero kernel ----------------
#define ZW (131072 + 512 + NN)
__global__ void zero_all_kernel() {
    int i = blockIdx.x * 256 + threadIdx.x;
    if (i < 131072) g_pooled[i] = 0.f;
    else if (i < 131072 + 512) g_stats[i - 131072] = 0.f;
    else if (i < ZW) g_deg[i - 131072 - 512] = 0;
}

// ---------------- CSR build ----------------
__global__ void hist_kernel(const int* __restrict__ ei) {
    int e = blockIdx.x * 256 + threadIdx.x;
    if (e < NE) atomicAdd(&g_deg[ei[NE + e]], 1);
}
__global__ void scan1_kernel() {                  // <<<NSB,1024>>>
    __shared__ int wsum[32];
    int tid = threadIdx.x;
    int i = blockIdx.x * 1024 + tid;
    int v = (i < NN) ? g_deg[i] : 0;
    int x = v;
    #pragma unroll
    for (int o = 1; o < 32; o <<= 1) {
        int t = __shfl_up_sync(0xffffffffu, x, o);
        if ((tid & 31) >= o) x += t;
    }
    if ((tid & 31) == 31) wsum[tid >> 5] = x;
    __syncthreads();
    if (tid < 32) {
        int y = wsum[tid];
        #pragma unroll
        for (int o = 1; o < 32; o <<= 1) {
            int t = __shfl_up_sync(0xffffffffu, y, o);
            if (tid >= o) y += t;
        }
        wsum[tid] = y;
    }
    __syncthreads();
    int base = (tid >= 32) ? wsum[(tid >> 5) - 1] : 0;
    int incl = x + base;
    if (i < NN) g_off[i] = incl - v;
    if (tid == 1023) g_bsum[blockIdx.x] = incl;
}
__global__ void scan2_kernel() {                  // <<<1,128>>>
    __shared__ int s[128];
    int tid = threadIdx.x;
    int v = (tid < NSB) ? g_bsum[tid] : 0;
    s[tid] = v; __syncthreads();
    for (int off = 1; off < 128; off <<= 1) {
        int t = (tid >= off) ? s[tid - off] : 0;
        __syncthreads();
        s[tid] += t;
        __syncthreads();
    }
    if (tid < NSB) g_boff[tid] = s[tid] - v;
}
__global__ void scan3_kernel() {                  // <<<NSB,1024>>>
    int i = blockIdx.x * 1024 + threadIdx.x;
    if (i < NN) {
        int v = g_off[i] + g_boff[blockIdx.x];
        g_off[i] = v;
        g_cursor[i] = v;
    }
    if (i == 0) g_off[NN] = NE;
}
__global__ void csr_scatter_kernel(const int* __restrict__ ei) {
    int e = blockIdx.x * 256 + threadIdx.x;
    if (e < NE) {
        int s = ei[e];
        int d = ei[NE + e];
        int p = atomicAdd(&g_cursor[d], 1);
        g_srcs[p] = s;
    }
}

// ---------------- gemm_pre: y = X @ W1_0 (F=128 -> 64, no bias), bf16 store ----------------
// block = 64 nodes, 8 warps; warp = 8 nodes x 64 ch
__global__ void __launch_bounds__(256) gemm_pre_kernel(
    const float* __restrict__ X, const float* __restrict__ W, int N)
{
    constexpr int F = 128;
    __shared__ float xs[F * 68];       // [k][node], stride 68 (16B-aligned quads)
    __shared__ float ws[F * 64];
    int tid = threadIdx.x;

    const float4* Wv = (const float4*)W;
    float4* wsv = (float4*)ws;
    #pragma unroll
    for (int i = tid; i < F * 16; i += 256) wsv[i] = Wv[i];

    int base = blockIdx.x * 64;
    int n = tid & 63, q0 = tid >> 6;         // q0 in 0..3
    int row = base + n;
    const float4* Xv = (const float4*)X;
    #pragma unroll
    for (int q = q0; q < F / 4; q += 4) {
        float4 v = make_float4(0.f, 0.f, 0.f, 0.f);
        if (row < N) v = Xv[row * (F / 4) + q];
        xs[(4 * q + 0) * 68 + n] = v.x;
        xs[(4 * q + 1) * 68 + n] = v.y;
        xs[(4 * q + 2) * 68 + n] = v.z;
        xs[(4 * q + 3) * 68 + n] = v.w;
    }
    __syncthreads();

    int w8 = (tid >> 5) * 8;
    int cp = tid & 31;
    int c = cp * 2;
    unsigned long long acc[4][2];
    #pragma unroll
    for (int p = 0; p < 4; p++) { acc[p][0] = 0ull; acc[p][1] = 0ull; }
    #pragma unroll 4
    for (int k = 0; k < F; k++) {
        ulonglong2 xa = *(const ulonglong2*)&xs[k * 68 + w8];       // nodes 0-3
        ulonglong2 xb = *(const ulonglong2*)&xs[k * 68 + w8 + 4];   // nodes 4-7
        float2 wv = *(const float2*)&ws[k * 64 + c];
        unsigned long long wx = f32x2_dup(wv.x), wy = f32x2_dup(wv.y);
        f32x2_fma(acc[0][0], xa.x, wx); f32x2_fma(acc[0][1], xa.x, wy);
        f32x2_fma(acc[1][0], xa.y, wx); f32x2_fma(acc[1][1], xa.y, wy);
        f32x2_fma(acc[2][0], xb.x, wx); f32x2_fma(acc[2][1], xb.x, wy);
        f32x2_fma(acc[3][0], xb.y, wx); f32x2_fma(acc[3][1], xb.y, wy);
    }
    #pragma unroll
    for (int p = 0; p < 4; p++) {
        float2 u0 = f32x2_unpack(acc[p][0]);   // {node 2p, node 2p+1} ch c
        float2 u1 = f32x2_unpack(acc[p][1]);   // ch c+1
        int r0 = base + w8 + 2 * p, r1 = r0 + 1;
        if (r0 < N) g_yb[r0 * 32 + cp] = __floats2bfloat162_rn(u0.x, u1.x);
        if (r1 < N) g_yb[r1 * 32 + cp] = __floats2bfloat162_rn(u0.y, u1.y);
    }
}

// ---------------- aggregate: t[n] = (1+eps)*y[n] + sum_nb y + b1; fused BN stats ----------------
__global__ void __launch_bounds__(256) aggregate_kernel(
    const float* __restrict__ eps_arr, int layer, const float* __restrict__ b1)
{
    __shared__ float ss[128];
    int tid = threadIdx.x;
    if (tid < 128) ss[tid] = 0.f;
    __syncthreads();

    int warp = (blockIdx.x * 256 + tid) >> 5;
    int lane = tid & 31;
    if (warp < NN) {
        float oe = 1.0f + __ldg(&eps_arr[layer]);
        int beg = g_off[warp], end = g_off[warp + 1];
        float2 self = __bfloat1622float2(g_yb[warp * 32 + lane]);
        float2 acc = make_float2(self.x * oe, self.y * oe);
        for (int bse = beg; bse < end; bse += 32) {
            int m = end - bse; if (m > 32) m = 32;
            int idx = (lane < m) ? g_srcs[bse + lane] : 0;
            int t = 0;
            for (; t + 4 <= m; t += 4) {
                int s0 = __shfl_sync(0xffffffffu, idx, t);
                int s1 = __shfl_sync(0xffffffffu, idx, t + 1);
                int s2 = __shfl_sync(0xffffffffu, idx, t + 2);
                int s3 = __shfl_sync(0xffffffffu, idx, t + 3);
                float2 a = __bfloat1622float2(g_yb[s0 * 32 + lane]);
                float2 b = __bfloat1622float2(g_yb[s1 * 32 + lane]);
                float2 cc = __bfloat1622float2(g_yb[s2 * 32 + lane]);
                float2 d = __bfloat1622float2(g_yb[s3 * 32 + lane]);
                acc.x += (a.x + b.x) + (cc.x + d.x);
                acc.y += (a.y + b.y) + (cc.y + d.y);
            }
            for (; t < m; t++) {
                int s0 = __shfl_sync(0xffffffffu, idx, t);
                float2 a = __bfloat1622float2(g_yb[s0 * 32 + lane]);
                acc.x += a.x; acc.y += a.y;
            }
        }
        float2 bb = *(const float2*)&b1[2 * lane];
        acc.x += bb.x; acc.y += bb.y;
        *(float2*)&g_t[warp * 64 + 2 * lane] = acc;
        atomicAdd(&ss[2 * lane], acc.x);
        atomicAdd(&ss[2 * lane + 1], acc.y);
        atomicAdd(&ss[64 + 2 * lane], acc.x * acc.x);
        atomicAdd(&ss[64 + 2 * lane + 1], acc.y * acc.y);
    }
    __syncthreads();
    if (tid < 128) atomicAdd(&g_stats[layer * 128 + tid], ss[tid]);
}

// ---------------- gemm_dual: z=relu(bn(t)); H=relu(z@W2+b2); pool H; y_next=H@W1n (bf16) ----------------
// block = 128 nodes, 8 warps; warp = 16 nodes x 64 ch (node pairs in f32x2)
__global__ void __launch_bounds__(256) gemm_dual_kernel(
    const float* __restrict__ W2, const float* __restrict__ B2,
    const int* __restrict__ batch, int pool_off,
    const float* __restrict__ W1n, int has_next, int N,
    int layer, const float* __restrict__ gg, const float* __restrict__ be, float ninv)
{
    __shared__ float xs[64 * 132];    // [k][node], stride 132 (16B-aligned)
    __shared__ float ws2s[64 * 64];
    __shared__ float ws1s[64 * 64];
    __shared__ float scs[64], shs[64];
    int tid = threadIdx.x;

    {
        const float4* Wv = (const float4*)W2;
        float4* dv = (float4*)ws2s;
        #pragma unroll
        for (int i = tid; i < 1024; i += 256) dv[i] = Wv[i];
    }
    if (has_next) {
        const float4* Wv = (const float4*)W1n;
        float4* dv = (float4*)ws1s;
        #pragma unroll
        for (int i = tid; i < 1024; i += 256) dv[i] = Wv[i];
    }
    if (tid < 64) {
        float mean = g_stats[layer * 128 + tid] * ninv;
        float var  = g_stats[layer * 128 + 64 + tid] * ninv - mean * mean;
        float s = gg[tid] * rsqrtf(var + 1e-5f);
        scs[tid] = s;
        shs[tid] = fmaf(-mean, s, be[tid]);
    }
    __syncthreads();

    int base = blockIdx.x * 128;
    int n = tid & 127, q0 = tid >> 7;    // q0 in 0..1
    int row = base + n;
    const float4* Tv = (const float4*)g_t;
    #pragma unroll
    for (int q = q0; q < 16; q += 2) {
        float4 v = make_float4(0.f, 0.f, 0.f, 0.f);
        if (row < N) {
            float4 t = Tv[row * 16 + q];
            int cb = q * 4;
            v.x = fmaxf(fmaf(t.x, scs[cb + 0], shs[cb + 0]), 0.f);
            v.y = fmaxf(fmaf(t.y, scs[cb + 1], shs[cb + 1]), 0.f);
            v.z = fmaxf(fmaf(t.z, scs[cb + 2], shs[cb + 2]), 0.f);
            v.w = fmaxf(fmaf(t.w, scs[cb + 3], shs[cb + 3]), 0.f);
        }
        xs[(4 * q + 0) * 132 + n] = v.x;
        xs[(4 * q + 1) * 132 + n] = v.y;
        xs[(4 * q + 2) * 132 + n] = v.z;
        xs[(4 * q + 3) * 132 + n] = v.w;
    }
    __syncthreads();

    int w16 = (tid >> 5) * 16;
    int cp = tid & 31;
    int c = cp * 2;
    float2 bb = *(const float2*)&B2[c];
    unsigned long long acc[8][2];
    #pragma unroll
    for (int p = 0; p < 8; p++) { acc[p][0] = f32x2_dup(bb.x); acc[p][1] = f32x2_dup(bb.y); }
    #pragma unroll 4
    for (int k = 0; k < 64; k++) {
        ulonglong2 xa = *(const ulonglong2*)&xs[k * 132 + w16];        // nodes 0-3
        ulonglong2 xb = *(const ulonglong2*)&xs[k * 132 + w16 + 4];    // nodes 4-7
        ulonglong2 xc = *(const ulonglong2*)&xs[k * 132 + w16 + 8];    // nodes 8-11
        ulonglong2 xd = *(const ulonglong2*)&xs[k * 132 + w16 + 12];   // nodes 12-15
        float2 wv = *(const float2*)&ws2s[k * 64 + c];
        unsigned long long wx = f32x2_dup(wv.x), wy = f32x2_dup(wv.y);
        f32x2_fma(acc[0][0], xa.x, wx); f32x2_fma(acc[0][1], xa.x, wy);
        f32x2_fma(acc[1][0], xa.y, wx); f32x2_fma(acc[1][1], xa.y, wy);
        f32x2_fma(acc[2][0], xb.x, wx); f32x2_fma(acc[2][1], xb.x, wy);
        f32x2_fma(acc[3][0], xb.y, wx); f32x2_fma(acc[3][1], xb.y, wy);
        f32x2_fma(acc[4][0], xc.x, wx); f32x2_fma(acc[4][1], xc.x, wy);
        f32x2_fma(acc[5][0], xc.y, wx); f32x2_fma(acc[5][1], xc.y, wy);
        f32x2_fma(acc[6][0], xd.x, wx); f32x2_fma(acc[6][1], xd.x, wy);
        f32x2_fma(acc[7][0], xd.y, wx); f32x2_fma(acc[7][1], xd.y, wy);
    }
    float H[16][2];
    #pragma unroll
    for (int p = 0; p < 8; p++) {
        float2 u0 = f32x2_unpack(acc[p][0]);   // {node 2p, node 2p+1} ch c
        float2 u1 = f32x2_unpack(acc[p][1]);   // ch c+1
        H[2 * p + 0][0] = fmaxf(u0.x, 0.f); H[2 * p + 0][1] = fmaxf(u1.x, 0.f);
        H[2 * p + 1][0] = fmaxf(u0.y, 0.f); H[2 * p + 1][1] = fmaxf(u1.y, 0.f);
    }

    // pooling (batch sorted -> run-compressed atomics)
    int rbase = base + w16;
    int bprev = -1; float p0 = 0.f, p1 = 0.f;
    #pragma unroll
    for (int j = 0; j < 16; j++) {
        int r = rbase + j;
        if (r < N) {
            int bg = batch[r];
            if (bg != bprev) {
                if (bprev >= 0)
                    atomicAdd((float2*)&g_pooled[bprev * 256 + pool_off + c], make_float2(p0, p1));
                bprev = bg; p0 = 0.f; p1 = 0.f;
            }
            p0 += H[j][0]; p1 += H[j][1];
        }
    }
    if (bprev >= 0)
        atomicAdd((float2*)&g_pooled[bprev * 256 + pool_off + c], make_float2(p0, p1));

    if (has_next) {
        // transposed warp-private store of H, then second GEMM
        #pragma unroll
        for (int p = 0; p < 8; p++) {
            *(float2*)&xs[c * 132 + w16 + 2 * p]       = make_float2(H[2 * p][0], H[2 * p + 1][0]);
            *(float2*)&xs[(c + 1) * 132 + w16 + 2 * p] = make_float2(H[2 * p][1], H[2 * p + 1][1]);
        }
        __syncwarp();
        unsigned long long acc2[8][2];
        #pragma unroll
        for (int p = 0; p < 8; p++) { acc2[p][0] = 0ull; acc2[p][1] = 0ull; }
        #pragma unroll 4
        for (int k = 0; k < 64; k++) {
            ulonglong2 xa = *(const ulonglong2*)&xs[k * 132 + w16];
            ulonglong2 xb = *(const ulonglong2*)&xs[k * 132 + w16 + 4];
            ulonglong2 xc = *(const ulonglong2*)&xs[k * 132 + w16 + 8];
            ulonglong2 xd = *(const ulonglong2*)&xs[k * 132 + w16 + 12];
            float2 wv = *(const float2*)&ws1s[k * 64 + c];
            unsigned long long wx = f32x2_dup(wv.x), wy = f32x2_dup(wv.y);
            f32x2_fma(acc2[0][0], xa.x, wx); f32x2_fma(acc2[0][1], xa.x, wy);
            f32x2_fma(acc2[1][0], xa.y, wx); f32x2_fma(acc2[1][1], xa.y, wy);
            f32x2_fma(acc2[2][0], xb.x, wx); f32x2_fma(acc2[2][1], xb.x, wy);
            f32x2_fma(acc2[3][0], xb.y, wx); f32x2_fma(acc2[3][1], xb.y, wy);
            f32x2_fma(acc2[4][0], xc.x, wx); f32x2_fma(acc2[4][1], xc.x, wy);
            f32x2_fma(acc2[5][0], xc.y, wx); f32x2_fma(acc2[5][1], xc.y, wy);
            f32x2_fma(acc2[6][0], xd.x, wx); f32x2_fma(acc2[6][1], xd.x, wy);
            f32x2_fma(acc2[7][0], xd.y, wx); f32x2_fma(acc2[7][1], xd.y, wy);
        }
        #pragma unroll
        for (int p = 0; p < 8; p++) {
            float2 u0 = f32x2_unpack(acc2[p][0]);
            float2 u1 = f32x2_unpack(acc2[p][1]);
            int r0 = rbase + 2 * p, r1 = r0 + 1;
            if (r0 < N) g_yb[r0 * 32 + cp] = __floats2bfloat162_rn(u0.x, u1.x);
            if (r1 < N) g_yb[r1 * 32 + cp] = __floats2bfloat162_rn(u0.y, u1.y);
        }
    }
}

// ---------------- head ----------------
__global__ void head1_kernel(const float* __restrict__ W, const float* __restrict__ B)
{
    int gph = blockIdx.x, c = threadIdx.x;   // <<<512,64>>>
    __shared__ float xs[256];
    #pragma unroll
    for (int i = c; i < 256; i += 64) xs[i] = g_pooled[gph * 256 + i];
    __syncthreads();
    float a = B[c];
    #pragma unroll 4
    for (int k = 0; k < 256; k++) a = fmaf(xs[k], __ldg(&W[k * 64 + c]), a);
    g_head1[gph * 64 + c] = a;
}

__global__ void head_bn_kernel(const float* __restrict__ g, const float* __restrict__ be)
{
    int c = blockIdx.x; int t = threadIdx.x;  // <<<64,256>>>
    __shared__ float red[256];
    float v0 = g_head1[t * 64 + c];
    float v1 = g_head1[(t + 256) * 64 + c];
    red[t] = v0 + v1;
    __syncthreads();
    for (int o = 128; o > 0; o >>= 1) { if (t < o) red[t] += red[t + o]; __syncthreads(); }
    float mean = red[0] * (1.0f / 512.0f);
    __syncthreads();
    float d0 = v0 - mean, d1 = v1 - mean;
    red[t] = d0 * d0 + d1 * d1;
    __syncthreads();
    for (int o = 128; o > 0; o >>= 1) { if (t < o) red[t] += red[t + o]; __syncthreads(); }
    if (t == 0) {
        float var = red[0] * (1.0f / 512.0f);
        float s = g[c] * rsqrtf(var + 1e-5f);
        g_scale[c] = s;
        g_shift[c] = fmaf(-mean, s, be[c]);
    }
}

__global__ void head_final_kernel(const float* __restrict__ W, const float* __restrict__ B,
                                  float* __restrict__ out)
{
    int gph = blockIdx.x; int c = threadIdx.x;   // <<<512,64>>>
    __shared__ float hn[64];
    __shared__ float logits[10];
    hn[c] = fmaxf(fmaf(g_head1[gph * 64 + c], g_scale[c], g_shift[c]), 0.f);
    __syncthreads();
    if (c < 10) {
        float a = B[c];
        #pragma unroll
        for (int k = 0; k < 64; k++) a = fmaf(hn[k], W[k * 10 + c], a);
        logits[c] = a;
    }
    __syncthreads();
    if (c == 0) {
        float m = logits[0];
        #pragma unroll
        for (int j = 1; j < 10; j++) m = fmaxf(m, logits[j]);
        float ssum = 0.f;
        #pragma unroll
        for (int j = 0; j < 10; j++) ssum += expf(logits[j] - m);
        float lse = m + logf(ssum);
        #pragma unroll
        for (int j = 0; j < 10; j++) out[gph * 10 + j] = logits[j] - lse;
    }
}

// ---------------- launch ----------------
extern "C" void kernel_launch(void* const* d_in, const int* in_sizes, int n_in,
                              void* d_out, int out_size)
{
    const float* x     = (const float*)d_in[0];
    const int*   ei    = (const int*)d_in[1];
    const int*   batch = (const int*)d_in[2];
    const float* eps   = (const float*)d_in[3];

    zero_all_kernel<<<(ZW + 255) / 256, 256>>>();                 // 1
    hist_kernel<<<(NE + 255) / 256, 256>>>(ei);                   // 2
    scan1_kernel<<<NSB, 1024>>>();                                // 3
    // gemm_pre independent of the scans -> profiled slot 4
    gemm_pre_kernel<<<(NN + 63) / 64, 256>>>(x, (const float*)d_in[4], NN);  // 4
    scan2_kernel<<<1, 128>>>();                                   // 5
    scan3_kernel<<<NSB, 1024>>>();                                // 6
    csr_scatter_kernel<<<(NE + 255) / 256, 256>>>(ei);            // 7

    for (int l = 0; l < 4; l++) {
        const float *b1, *gg, *be, *W2, *b2;
        if (l == 0) {
            b1 = (const float*)d_in[5];
            gg = (const float*)d_in[6]; be = (const float*)d_in[7];
            W2 = (const float*)d_in[8]; b2 = (const float*)d_in[9];
        } else {
            int j = l - 1;
            b1 = (const float*)d_in[11] + j * 64;
            gg = (const float*)d_in[12] + j * 64; be = (const float*)d_in[13] + j * 64;
            W2 = (const float*)d_in[14] + j * 64 * 64; b2 = (const float*)d_in[15] + j * 64;
        }
        const float* W1n = (l < 3) ? ((const float*)d_in[10] + l * 64 * 64) : (const float*)d_in[10];
        int has_next = (l < 3) ? 1 : 0;

        aggregate_kernel<<<(NN * 32 + 255) / 256, 256>>>(eps, l, b1);
        gemm_dual_kernel<<<(NN + 127) / 128, 256>>>(W2, b2, batch, l * 64, W1n, has_next, NN,
                                                    l, gg, be, 1.0f / (float)NN);
    }

    head1_kernel<<<NG, 64>>>((const float*)d_in[16], (const float*)d_in[17]);
    head_bn_kernel<<<64, 256>>>((const float*)d_in[18], (const float*)d_in[19]);
    head_final_kernel<<<NG, 64>>>((const float*)d_in[20], (const float*)d_in[21], (float*)d_out);
}